// round 3
// baseline (speedup 1.0000x reference)
#include <cuda_runtime.h>

// Problem sizes (fixed by the reference)
#define BB 32
#define TT 512
#define EE 1024
#define HH 1024

// ---------------------------------------------------------------------------
// f32x2 packed-FMA helpers (sm_103a FFMA2 path; ptxas only emits via PTX)
// ---------------------------------------------------------------------------
static __device__ __forceinline__ void fma2(unsigned long long &acc,
                                            unsigned long long a,
                                            unsigned long long b) {
    asm("fma.rn.f32x2 %0, %1, %2, %0;" : "+l"(acc) : "l"(a), "l"(b));
}
static __device__ __forceinline__ float2 unpk(unsigned long long v) {
    float2 r;
    asm("mov.b64 {%0, %1}, %2;" : "=f"(r.x), "=f"(r.y) : "l"(v));
    return r;
}

// ---------------------------------------------------------------------------
// Global scratch: ping-pong hidden state + device-wide barrier counter
// ---------------------------------------------------------------------------
__device__ float        g_h[2][BB * HH];
__device__ unsigned int g_cnt;

__global__ void init_kernel() {
    int i = blockIdx.x * blockDim.x + threadIdx.x;
    if (i == 0) g_cnt = 0u;
    if (i < BB * HH) g_h[0][i] = 0.0f;   // h_0 = 0
}

// ---------------------------------------------------------------------------
// Phase 1: out[m][n] = sum_k X[m][k] * W[n][k] + (bih[n] + bhh[n])
// M = B*T = 16384, N = H = 1024, K = E = 1024. Both operands K-major (NT GEMM).
// CTA tile 128x64, BK=32, 256 threads, 8x4 microtile per thread, FFMA2.
// Lane map r=tid&15 -> rows (r+16i), c=tid>>4 -> cols (c+16j):
//   A LDS.128: per phase of 8 lanes one unique address (broadcast)
//   B LDS.128: two unique addresses per warp (broadcast)     -> conflict-free
// ---------------------------------------------------------------------------
#define BM  128
#define BN  64
#define BK  32
#define LDA 36   // 32 + 4 pad, keeps 16B alignment, conflict-free phases

__global__ __launch_bounds__(256) void gemm_xp_kernel(
    const float* __restrict__ X, const float* __restrict__ W,
    const float* __restrict__ bih, const float* __restrict__ bhh,
    float* __restrict__ out)
{
    __shared__ __align__(16) float As[BM * LDA];
    __shared__ __align__(16) float Bs[BN * LDA];

    const int tid = threadIdx.x;
    const int m0  = blockIdx.y * BM;
    const int n0  = blockIdx.x * BN;
    const int r   = tid & 15;
    const int c   = tid >> 4;

    unsigned long long acc[8][4];
#pragma unroll
    for (int i = 0; i < 8; i++)
#pragma unroll
        for (int j = 0; j < 4; j++) acc[i][j] = 0ull;

    for (int kt = 0; kt < EE; kt += BK) {
        // Stage A tile: 128 rows x 32 floats = 1024 float4 (4 per thread)
#pragma unroll
        for (int u = 0; u < 4; u++) {
            int f = tid + u * 256;
            int row = f >> 3, kk = (f & 7) << 2;
            *(float4*)&As[row * LDA + kk] =
                *(const float4*)&X[(m0 + row) * EE + kt + kk];
        }
        // Stage B tile: 64 rows x 32 floats = 512 float4 (2 per thread)
#pragma unroll
        for (int u = 0; u < 2; u++) {
            int f = tid + u * 256;
            int row = f >> 3, kk = (f & 7) << 2;
            *(float4*)&Bs[row * LDA + kk] =
                *(const float4*)&W[(n0 + row) * EE + kt + kk];
        }
        __syncthreads();

#pragma unroll
        for (int kk = 0; kk < BK; kk += 4) {
            ulonglong2 av[8];
            ulonglong2 bv[4];
#pragma unroll
            for (int i = 0; i < 8; i++)
                av[i] = *(const ulonglong2*)&As[(r + 16 * i) * LDA + kk];
#pragma unroll
            for (int j = 0; j < 4; j++)
                bv[j] = *(const ulonglong2*)&Bs[(c + 16 * j) * LDA + kk];
#pragma unroll
            for (int i = 0; i < 8; i++) {
#pragma unroll
                for (int j = 0; j < 4; j++) {
                    fma2(acc[i][j], av[i].x, bv[j].x);
                    fma2(acc[i][j], av[i].y, bv[j].y);
                }
            }
        }
        __syncthreads();
    }

#pragma unroll
    for (int j = 0; j < 4; j++) {
        int n = n0 + c + 16 * j;
        float bias = bih[n] + bhh[n];
#pragma unroll
        for (int i = 0; i < 8; i++) {
            float2 v = unpk(acc[i][j]);
            out[(m0 + r + 16 * i) * HH + n] = v.x + v.y + bias;
        }
    }
}

// ---------------------------------------------------------------------------
// Phase 2: persistent recurrence kernel.
// 128 CTAs (all co-resident on 148 SMs), 256 threads.
//   batch group gb = blockIdx.x>>5   -> batches [gb*8, gb*8+8)
//   col block   cb = blockIdx.x&31   -> columns [cb*32, cb*32+32)
// Each CTA caches its 32 W_hh rows (128 KB) in smem once, and stages its
// 8 h rows (33 KB) from L2 (__ldcg, ping-pong buffers) every step.
// Thread (b = tid&7, cl = tid>>3) computes one output: FFMA2 dot over K=1024.
// One device-wide barrier per step (monotonic atomic counter + L2 spin).
// ---------------------------------------------------------------------------
#define RGRID    128
#define HS_LD    1028                         // 1024 + 4 pad (conflict-free)
#define RSM_FLT  (32 * 1024 + 8 * HS_LD)
#define RSM_BYTES (RSM_FLT * 4)

__global__ __launch_bounds__(256) void rnn_rec_kernel(
    const float* __restrict__ Whh, float* __restrict__ out)
{
    extern __shared__ __align__(16) float sm[];
    float* Ws = sm;              // [32][1024] W_hh rows for this CTA's columns
    float* hs = sm + 32 * 1024;  // [8][HS_LD] hidden-state slice

    const int tid  = threadIdx.x;
    const int gb   = blockIdx.x >> 5;
    const int c0   = (blockIdx.x & 31) * 32;
    const int b    = tid & 7;          // local batch
    const int cl   = tid >> 3;         // local column 0..31
    const int bg   = gb * 8 + b;       // global batch
    const int colg = c0 + cl;          // global column

    // Stage W_hh rows [c0, c0+32) : 8192 float4, 32 per thread (coalesced)
#pragma unroll 4
    for (int u = 0; u < 32; u++) {
        int f = tid + u * 256;
        int row = f >> 8, kk = (f & 255) << 2;
        *(float4*)&Ws[row * 1024 + kk] =
            *(const float4*)&Whh[(c0 + row) * HH + kk];
    }

    const float* wrow  = &Ws[cl * 1024];
    const float* hrow  = &hs[b * HS_LD];
    const int    hwidx = bg * HH + colg;
    const int    obase = bg * TT * HH + colg;

    for (int t = 0; t < TT; t++) {
        // Stage this group's 8 h rows (32 KB contiguous) from L2
        const float4* hsrc = (const float4*)(g_h[t & 1] + gb * 8 * HH);
#pragma unroll
        for (int u = 0; u < 8; u++) {
            int f = tid + u * 256;                 // float4 index 0..2047
            float4 v = __ldcg(hsrc + f);
            int row = f >> 8, kk = (f & 255) << 2;
            *(float4*)&hs[row * HS_LD + kk] = v;
        }
        __syncthreads();

        unsigned long long acca = 0ull, accb = 0ull;
#pragma unroll 16
        for (int k = 0; k < HH; k += 4) {
            ulonglong2 hv = *(const ulonglong2*)&hrow[k];
            ulonglong2 wv = *(const ulonglong2*)&wrow[k];
            fma2(acca, hv.x, wv.x);
            fma2(accb, hv.y, wv.y);
        }
        float2 va = unpk(acca), vb = unpk(accb);
        float s = (va.x + va.y) + (vb.x + vb.y);

        int oi = obase + t * HH;
        float hnew = tanhf(out[oi] + s);   // out holds xp (+bias) from phase 1
        out[oi] = hnew;
        g_h[(t + 1) & 1][hwidx] = hnew;

        // Device-wide barrier (all 128 CTAs are co-resident)
        __threadfence();
        __syncthreads();
        if (tid == 0) {
            atomicAdd(&g_cnt, 1u);
            unsigned int target = (unsigned int)(t + 1) * RGRID;
            volatile unsigned int* p = &g_cnt;
            while (*p < target) { }
        }
        __syncthreads();
    }
}

// ---------------------------------------------------------------------------
// Launch: init (zero h0 + barrier) -> input-projection GEMM -> recurrence
// ---------------------------------------------------------------------------
extern "C" void kernel_launch(void* const* d_in, const int* in_sizes, int n_in,
                              void* d_out, int out_size)
{
    const float* x   = (const float*)d_in[0];
    const float* Wih = (const float*)d_in[1];
    const float* Whh = (const float*)d_in[2];
    const float* bih = (const float*)d_in[3];
    const float* bhh = (const float*)d_in[4];
    float* out = (float*)d_out;
    (void)in_sizes; (void)n_in; (void)out_size;

    cudaFuncSetAttribute(rnn_rec_kernel,
                         cudaFuncAttributeMaxDynamicSharedMemorySize,
                         RSM_BYTES);

    init_kernel<<<128, 256>>>();

    dim3 g1(HH / BN, (BB * TT) / BM);   // (16, 128)
    gemm_xp_kernel<<<g1, 256>>>(x, Wih, bih, bhh, out);

    rnn_rec_kernel<<<RGRID, 256, RSM_BYTES>>>(Whh, out);
}

// round 4
// speedup vs baseline: 1.8008x; 1.8008x over previous
#include <cuda_runtime.h>

// Problem sizes (fixed by the reference)
#define BB 32
#define TT 512
#define EE 1024
#define HH 1024

// ---------------------------------------------------------------------------
// f32x2 packed-FMA helpers (sm_103a FFMA2 path; ptxas only emits via PTX)
// ---------------------------------------------------------------------------
static __device__ __forceinline__ void fma2(unsigned long long &acc,
                                            unsigned long long a,
                                            unsigned long long b) {
    asm("fma.rn.f32x2 %0, %1, %2, %0;" : "+l"(acc) : "l"(a), "l"(b));
}
static __device__ __forceinline__ float2 unpk(unsigned long long v) {
    float2 r;
    asm("mov.b64 {%0, %1}, %2;" : "=f"(r.x), "=f"(r.y) : "l"(v));
    return r;
}

// ---------------------------------------------------------------------------
// Global scratch: ping-pong hidden state + device-wide barrier counter
// ---------------------------------------------------------------------------
__device__ float        g_h[2][BB * HH];
__device__ unsigned int g_cnt;

__global__ void init_kernel() {
    int i = blockIdx.x * blockDim.x + threadIdx.x;
    if (i == 0) g_cnt = 0u;
    if (i < BB * HH) g_h[0][i] = 0.0f;   // h_0 = 0
}

// ---------------------------------------------------------------------------
// Phase 1: out[m][n] = sum_k X[m][k] * W[n][k] + (bih[n] + bhh[n])
// M = B*T = 16384, N = H = 1024, K = E = 1024, NT GEMM, FFMA2, 128x64 tile.
// (Measured-consistent ~0.6 ms; compute-bound; unchanged from R2.)
// ---------------------------------------------------------------------------
#define BM  128
#define BN  64
#define BK  32
#define LDA 36

__global__ __launch_bounds__(256) void gemm_xp_kernel(
    const float* __restrict__ X, const float* __restrict__ W,
    const float* __restrict__ bih, const float* __restrict__ bhh,
    float* __restrict__ out)
{
    __shared__ __align__(16) float As[BM * LDA];
    __shared__ __align__(16) float Bs[BN * LDA];

    const int tid = threadIdx.x;
    const int m0  = blockIdx.y * BM;
    const int n0  = blockIdx.x * BN;
    const int r   = tid & 15;
    const int c   = tid >> 4;

    unsigned long long acc[8][4];
#pragma unroll
    for (int i = 0; i < 8; i++)
#pragma unroll
        for (int j = 0; j < 4; j++) acc[i][j] = 0ull;

    for (int kt = 0; kt < EE; kt += BK) {
#pragma unroll
        for (int u = 0; u < 4; u++) {
            int f = tid + u * 256;
            int row = f >> 3, kk = (f & 7) << 2;
            *(float4*)&As[row * LDA + kk] =
                *(const float4*)&X[(m0 + row) * EE + kt + kk];
        }
#pragma unroll
        for (int u = 0; u < 2; u++) {
            int f = tid + u * 256;
            int row = f >> 3, kk = (f & 7) << 2;
            *(float4*)&Bs[row * LDA + kk] =
                *(const float4*)&W[(n0 + row) * EE + kt + kk];
        }
        __syncthreads();

#pragma unroll
        for (int kk = 0; kk < BK; kk += 4) {
            ulonglong2 av[8];
            ulonglong2 bv[4];
#pragma unroll
            for (int i = 0; i < 8; i++)
                av[i] = *(const ulonglong2*)&As[(r + 16 * i) * LDA + kk];
#pragma unroll
            for (int j = 0; j < 4; j++)
                bv[j] = *(const ulonglong2*)&Bs[(c + 16 * j) * LDA + kk];
#pragma unroll
            for (int i = 0; i < 8; i++) {
#pragma unroll
                for (int j = 0; j < 4; j++) {
                    fma2(acc[i][j], av[i].x, bv[j].x);
                    fma2(acc[i][j], av[i].y, bv[j].y);
                }
            }
        }
        __syncthreads();
    }

#pragma unroll
    for (int j = 0; j < 4; j++) {
        int n = n0 + c + 16 * j;
        float bias = bih[n] + bhh[n];
#pragma unroll
        for (int i = 0; i < 8; i++) {
            float2 v = unpk(acc[i][j]);
            out[(m0 + r + 16 * i) * HH + n] = v.x + v.y + bias;
        }
    }
}

// ---------------------------------------------------------------------------
// Phase 2: persistent recurrence. 128 CTAs (co-resident), 256 threads.
//   CTA = batch group gb (8 batches) x col block (32 cols), full K = 1024.
//   Thread (c2 = tid&7 -> col quad of 4, ks = tid>>3 -> 32-wide K chunk)
//   computes an 8 (batch) x 4 (col) x Kt=32 partial with FFMA2; KS=32
//   partials per output reduced through a 32 KB smem tile.
//
//   Bank swizzle (16B granule g = k/4 within a 1024-float row):
//     W: g' = (g&~7) | ((g ^ (g>>3) ^ col) & 7)   -> warp's 32 W addresses
//        tile all 32 banks (4-way = full 512B/4cyc rate)
//     h: g' = (g&~7) | ((g ^ (g>>3)) & 7)         -> warp's 4 unique h
//        addresses land on 4 distinct bank groups (broadcast, 1 phase)
// ---------------------------------------------------------------------------
#define RGRID   128
#define RW_FLT  (32 * 1024)   // W slice, swizzled     (128 KB)
#define RH_FLT  (8 * 1024)    // h slice, swizzled     ( 32 KB)
#define RR_FLT  (32 * 256)    // reduction partials    ( 32 KB)
#define RSM_BYTES ((RW_FLT + RH_FLT + RR_FLT) * 4)

__global__ __launch_bounds__(256, 1) void rnn_rec_kernel(
    const float* __restrict__ Whh, float* __restrict__ out)
{
    extern __shared__ __align__(16) float sm[];
    float* Ws  = sm;                     // [32 cols][1024] swizzled
    float* hs  = sm + RW_FLT;            // [8 batches][1024] swizzled
    float* red = sm + RW_FLT + RH_FLT;   // [32 ks][256 outputs]

    const int tid = threadIdx.x;
    const int gb  = blockIdx.x >> 5;          // batch group 0..3
    const int c0  = (blockIdx.x & 31) * 32;   // global col base
    const int c2  = tid & 7;                  // col quad 0..7
    const int ks  = tid >> 3;                 // k chunk 0..31

    // ---- Stage W slice (once), applying the W swizzle -------------------
#pragma unroll 4
    for (int u = 0; u < 32; u++) {
        int f   = tid + u * 256;          // float4 index 0..8191
        int col = f >> 8;                 // local col 0..31
        int g   = f & 255;                // granule
        int gp  = (g & ~7) | ((g ^ (g >> 3) ^ col) & 7);
        float4 v = *(const float4*)&Whh[(c0 + col) * HH + g * 4];
        *(float4*)&Ws[col * 1024 + gp * 4] = v;
    }

    // Per-thread invariant offsets
    const int kbase = ks * 32;            // float offset of this k chunk
    const int sxh   = ks & 7;             // h swizzle term
    int sxj[4];
    const float* wb[4];
#pragma unroll
    for (int j = 0; j < 4; j++) {
        int col = c2 * 4 + j;
        sxj[j] = (ks ^ col) & 7;
        wb[j]  = &Ws[col * 1024 + kbase];
    }
    const float* hb = &hs[kbase];

    // Output mapping for the epilogue: o = tid = b*32 + colL (coalesced)
    const int b_out   = tid >> 5;
    const int colL    = tid & 31;
    const int oi_base = (gb * 8 + b_out) * TT * HH + (c0 + colL);
    const int hw_idx  = (gb * 8 + b_out) * HH + (c0 + colL);

    for (int t = 0; t < TT; t++) {
        // ---- Stage this group's h rows (32 KB) with the h swizzle -------
        const float4* hsrc = (const float4*)(g_h[t & 1] + gb * 8 * HH);
#pragma unroll
        for (int u = 0; u < 8; u++) {
            int f  = tid + u * 256;       // float4 index 0..2047
            float4 v = __ldcg(hsrc + f);
            int i  = f >> 8;
            int g  = f & 255;
            int gp = (g & ~7) | ((g ^ (g >> 3)) & 7);
            *(float4*)&hs[i * 1024 + gp * 4] = v;
        }
        __syncthreads();

        // ---- 8x4 x Kt=32 FFMA2 microtile --------------------------------
        unsigned long long acc[8][4];
#pragma unroll
        for (int i = 0; i < 8; i++)
#pragma unroll
            for (int j = 0; j < 4; j++) acc[i][j] = 0ull;

#pragma unroll
        for (int kq = 0; kq < 8; kq++) {
            ulonglong2 hv[8];
            ulonglong2 wv[4];
            int ho = ((kq ^ sxh) & 7) * 4;
#pragma unroll
            for (int i = 0; i < 8; i++)
                hv[i] = *(const ulonglong2*)(hb + i * 1024 + ho);
#pragma unroll
            for (int j = 0; j < 4; j++)
                wv[j] = *(const ulonglong2*)(wb[j] + ((kq ^ sxj[j]) & 7) * 4);
#pragma unroll
            for (int i = 0; i < 8; i++) {
#pragma unroll
                for (int j = 0; j < 4; j++) {
                    fma2(acc[i][j], hv[i].x, wv[j].x);
                    fma2(acc[i][j], hv[i].y, wv[j].y);
                }
            }
        }

        // ---- Reduce KS=32 partials through smem -------------------------
#pragma unroll
        for (int i = 0; i < 8; i++) {
            float2 a0 = unpk(acc[i][0]), a1 = unpk(acc[i][1]);
            float2 a2 = unpk(acc[i][2]), a3 = unpk(acc[i][3]);
            float4 v;
            v.x = a0.x + a0.y; v.y = a1.x + a1.y;
            v.z = a2.x + a2.y; v.w = a3.x + a3.y;
            *(float4*)&red[ks * 256 + i * 32 + c2 * 4] = v;
        }
        __syncthreads();

        float s = 0.0f;
#pragma unroll
        for (int k = 0; k < 32; k++) s += red[k * 256 + tid];

        // ---- tanh + coalesced writes ------------------------------------
        int oi = oi_base + t * HH;
        float hnew = tanhf(out[oi] + s);   // out holds xp (+bias) from phase 1
        out[oi] = hnew;
        g_h[(t + 1) & 1][hw_idx] = hnew;

        // ---- Device-wide barrier (all 128 CTAs co-resident) -------------
        __threadfence();
        __syncthreads();
        if (tid == 0) {
            atomicAdd(&g_cnt, 1u);
            unsigned int target = (unsigned int)(t + 1) * RGRID;
            volatile unsigned int* p = &g_cnt;
            while (*p < target) { }
        }
        __syncthreads();
    }
}

// ---------------------------------------------------------------------------
// Launch: init (zero h0 + barrier) -> input-projection GEMM -> recurrence
// ---------------------------------------------------------------------------
extern "C" void kernel_launch(void* const* d_in, const int* in_sizes, int n_in,
                              void* d_out, int out_size)
{
    const float* x   = (const float*)d_in[0];
    const float* Wih = (const float*)d_in[1];
    const float* Whh = (const float*)d_in[2];
    const float* bih = (const float*)d_in[3];
    const float* bhh = (const float*)d_in[4];
    float* out = (float*)d_out;
    (void)in_sizes; (void)n_in; (void)out_size;

    cudaFuncSetAttribute(rnn_rec_kernel,
                         cudaFuncAttributeMaxDynamicSharedMemorySize,
                         RSM_BYTES);

    init_kernel<<<128, 256>>>();

    dim3 g1(HH / BN, (BB * TT) / BM);   // (16, 128)
    gemm_xp_kernel<<<g1, 256>>>(x, Wih, bih, bhh, out);

    rnn_rec_kernel<<<RGRID, 256, RSM_BYTES>>>(Whh, out);
}

// round 5
// speedup vs baseline: 1.8192x; 1.0102x over previous
#include <cuda_runtime.h>

// Problem sizes (fixed by the reference)
#define BB 32
#define TT 512
#define EE 1024
#define HH 1024

// ---------------------------------------------------------------------------
// f32x2 packed-FMA helpers (sm_103a FFMA2 path; ptxas only emits via PTX)
// ---------------------------------------------------------------------------
static __device__ __forceinline__ void fma2(unsigned long long &acc,
                                            unsigned long long a,
                                            unsigned long long b) {
    asm("fma.rn.f32x2 %0, %1, %2, %0;" : "+l"(acc) : "l"(a), "l"(b));
}
static __device__ __forceinline__ float2 unpk(unsigned long long v) {
    float2 r;
    asm("mov.b64 {%0, %1}, %2;" : "=f"(r.x), "=f"(r.y) : "l"(v));
    return r;
}
static __device__ __forceinline__ unsigned ld_acq(const unsigned* p) {
    unsigned v;
    asm volatile("ld.acquire.gpu.u32 %0, [%1];" : "=r"(v) : "l"(p));
    return v;
}
static __device__ __forceinline__ void st_rel(unsigned* p, unsigned v) {
    asm volatile("st.release.gpu.u32 [%0], %1;" :: "l"(p), "r"(v) : "memory");
}

// ---------------------------------------------------------------------------
// Global scratch: 3-deep hidden-state ring + per-CTA monotonic step flags
// ---------------------------------------------------------------------------
__device__ float    g_h[3][BB * HH];
__device__ unsigned g_flag[128 * 32];   // one flag per CTA, 128B stride

__global__ void init_kernel() {
    int i = blockIdx.x * blockDim.x + threadIdx.x;
    if (i < 128 * 32) g_flag[i] = 0u;
    if (i < BB * HH)  g_h[0][i] = 0.0f;   // h_0 = 0
}

// ---------------------------------------------------------------------------
// Phase 1: out[m][n] = sum_k X[m][k] * W[n][k] + (bih[n] + bhh[n])
// M = B*T = 16384, N = H = 1024, K = E = 1024, NT GEMM, FFMA2, 128x64 tile.
// ---------------------------------------------------------------------------
#define BM  128
#define BN  64
#define BK  32
#define LDA 36

__global__ __launch_bounds__(256) void gemm_xp_kernel(
    const float* __restrict__ X, const float* __restrict__ W,
    const float* __restrict__ bih, const float* __restrict__ bhh,
    float* __restrict__ out)
{
    __shared__ __align__(16) float As[BM * LDA];
    __shared__ __align__(16) float Bs[BN * LDA];

    const int tid = threadIdx.x;
    const int m0  = blockIdx.y * BM;
    const int n0  = blockIdx.x * BN;
    const int r   = tid & 15;
    const int c   = tid >> 4;

    unsigned long long acc[8][4];
#pragma unroll
    for (int i = 0; i < 8; i++)
#pragma unroll
        for (int j = 0; j < 4; j++) acc[i][j] = 0ull;

    for (int kt = 0; kt < EE; kt += BK) {
#pragma unroll
        for (int u = 0; u < 4; u++) {
            int f = tid + u * 256;
            int row = f >> 3, kk = (f & 7) << 2;
            *(float4*)&As[row * LDA + kk] =
                *(const float4*)&X[(m0 + row) * EE + kt + kk];
        }
#pragma unroll
        for (int u = 0; u < 2; u++) {
            int f = tid + u * 256;
            int row = f >> 3, kk = (f & 7) << 2;
            *(float4*)&Bs[row * LDA + kk] =
                *(const float4*)&W[(n0 + row) * EE + kt + kk];
        }
        __syncthreads();

#pragma unroll
        for (int kk = 0; kk < BK; kk += 4) {
            ulonglong2 av[8];
            ulonglong2 bv[4];
#pragma unroll
            for (int i = 0; i < 8; i++)
                av[i] = *(const ulonglong2*)&As[(r + 16 * i) * LDA + kk];
#pragma unroll
            for (int j = 0; j < 4; j++)
                bv[j] = *(const ulonglong2*)&Bs[(c + 16 * j) * LDA + kk];
#pragma unroll
            for (int i = 0; i < 8; i++) {
#pragma unroll
                for (int j = 0; j < 4; j++) {
                    fma2(acc[i][j], av[i].x, bv[j].x);
                    fma2(acc[i][j], av[i].y, bv[j].y);
                }
            }
        }
        __syncthreads();
    }

#pragma unroll
    for (int j = 0; j < 4; j++) {
        int n = n0 + c + 16 * j;
        float bias = bih[n] + bhh[n];
#pragma unroll
        for (int i = 0; i < 8; i++) {
            float2 v = unpk(acc[i][j]);
            out[(m0 + r + 16 * i) * HH + n] = v.x + v.y + bias;
        }
    }
}

// ---------------------------------------------------------------------------
// Phase 2: persistent recurrence. 128 CTAs (co-resident), 256 threads.
//   CTA = batch group gb (8 batches) x col block cb (32 cols), full K = 1024.
//   Thread (c2 = tid&7 -> col quad, ks = tid>>3 -> 32-wide K chunk) computes
//   an 8x4xKt=32 FFMA2 partial; KS=32 partials reduced via a 32 KB smem tile.
//
//   Sync: NO device barrier. Each CTA publishes "step t done" with one
//   release-store flag after its h-writes. Staging thread tid copies granule
//   tid (16B) of all 8 rows; that granule's producer is CTA (gb, tid>>3), so
//   the thread acquire-spins on exactly ONE flag. 3-deep h ring buffer makes
//   the <=1-step intra-group skew safe (writer of step t+1 targets
//   buf[(t+2)%3], disjoint from buf[t%3] that a laggard still reads).
// ---------------------------------------------------------------------------
#define RGRID   128
#define RW_FLT  (32 * 1024)   // W slice, swizzled     (128 KB)
#define RH_FLT  (8 * 1024)    // h slice, swizzled     ( 32 KB)
#define RR_FLT  (32 * 256)    // reduction partials    ( 32 KB)
#define RSM_BYTES ((RW_FLT + RH_FLT + RR_FLT) * 4)

__global__ __launch_bounds__(256, 1) void rnn_rec_kernel(
    const float* __restrict__ Whh, float* __restrict__ out)
{
    extern __shared__ __align__(16) float sm[];
    float* Ws  = sm;                     // [32 cols][1024] swizzled
    float* hs  = sm + RW_FLT;            // [8 batches][1024] swizzled
    float* red = sm + RW_FLT + RH_FLT;   // [32 ks][256 outputs]

    const int tid = threadIdx.x;
    const int gb  = blockIdx.x >> 5;          // batch group 0..3
    const int c0  = (blockIdx.x & 31) * 32;   // global col base
    const int c2  = tid & 7;                  // col quad 0..7
    const int ks  = tid >> 3;                 // k chunk 0..31

    // ---- Stage W slice (once), applying the W swizzle -------------------
#pragma unroll 4
    for (int u = 0; u < 32; u++) {
        int f   = tid + u * 256;          // float4 index 0..8191
        int col = f >> 8;                 // local col 0..31
        int g   = f & 255;                // granule
        int gp  = (g & ~7) | ((g ^ (g >> 3) ^ col) & 7);
        float4 v = *(const float4*)&Whh[(c0 + col) * HH + g * 4];
        *(float4*)&Ws[col * 1024 + gp * 4] = v;
    }

    // Per-thread invariant offsets
    const int kbase = ks * 32;            // float offset of this k chunk
    const int sxh   = ks & 7;             // h swizzle term
    int sxj[4];
    const float* wb[4];
#pragma unroll
    for (int j = 0; j < 4; j++) {
        int col = c2 * 4 + j;
        sxj[j] = (ks ^ col) & 7;
        wb[j]  = &Ws[col * 1024 + kbase];
    }
    const float* hb = &hs[kbase];

    // Staging: thread tid copies granule tid of 8 rows; its single producer
    // is CTA (gb, tid>>3).
    const unsigned* my_src_flag = &g_flag[(gb * 32 + (tid >> 3)) * 32];
    unsigned*       my_flag     = &g_flag[blockIdx.x * 32];
    {   // precompute staging swizzle for granule g = tid
        // gp = (g&~7) | ((g ^ (g>>3)) & 7)
    }
    const int g_st  = tid;
    const int gp_st = (g_st & ~7) | ((g_st ^ (g_st >> 3)) & 7);

    // Epilogue output mapping: o = tid = b*32 + colL (coalesced)
    const int b_out   = tid >> 5;
    const int colL    = tid & 31;
    const int oi_base = (gb * 8 + b_out) * TT * HH + (c0 + colL);
    const int hw_idx  = (gb * 8 + b_out) * HH + (c0 + colL);

    int cur = 0, nxt = 1, nnx = 2;        // rotating ring indices (t%3 ...)
    float xp_cur = __ldg(&out[oi_base]);  // prefetch xp for t = 0

    for (int t = 0; t < TT; t++) {
        // ---- Wait for this granule's producer, then stage 8 rows --------
        if (t) {
            while (ld_acq(my_src_flag) < (unsigned)t) { }
        }
        {
            const float4* hsrc =
                (const float4*)(g_h[cur] + gb * 8 * HH) + g_st;
            float4* hdst = (float4*)&hs[gp_st * 4];
#pragma unroll
            for (int u = 0; u < 8; u++) {
                float4 v = __ldcg(hsrc + u * 256);
                *(float4*)((char*)hdst + u * 4096) = v;
            }
        }
        __syncthreads();

        // ---- 8x4 x Kt=32 FFMA2 microtile --------------------------------
        unsigned long long acc[8][4];
#pragma unroll
        for (int i = 0; i < 8; i++)
#pragma unroll
            for (int j = 0; j < 4; j++) acc[i][j] = 0ull;

#pragma unroll
        for (int kq = 0; kq < 8; kq++) {
            ulonglong2 hv[8];
            ulonglong2 wv[4];
            int ho = ((kq ^ sxh) & 7) * 4;
#pragma unroll
            for (int i = 0; i < 8; i++)
                hv[i] = *(const ulonglong2*)(hb + i * 1024 + ho);
#pragma unroll
            for (int j = 0; j < 4; j++)
                wv[j] = *(const ulonglong2*)(wb[j] + ((kq ^ sxj[j]) & 7) * 4);
#pragma unroll
            for (int i = 0; i < 8; i++) {
#pragma unroll
                for (int j = 0; j < 4; j++) {
                    fma2(acc[i][j], hv[i].x, wv[j].x);
                    fma2(acc[i][j], hv[i].y, wv[j].y);
                }
            }
        }

        // ---- Reduce KS=32 partials through smem -------------------------
#pragma unroll
        for (int i = 0; i < 8; i++) {
            float2 a0 = unpk(acc[i][0]), a1 = unpk(acc[i][1]);
            float2 a2 = unpk(acc[i][2]), a3 = unpk(acc[i][3]);
            float4 v;
            v.x = a0.x + a0.y; v.y = a1.x + a1.y;
            v.z = a2.x + a2.y; v.w = a3.x + a3.y;
            *(float4*)&red[ks * 256 + i * 32 + c2 * 4] = v;
        }
        __syncthreads();

        float s0 = 0.f, s1 = 0.f, s2 = 0.f, s3 = 0.f;
#pragma unroll
        for (int k = 0; k < 32; k += 4) {
            s0 += red[(k + 0) * 256 + tid];
            s1 += red[(k + 1) * 256 + tid];
            s2 += red[(k + 2) * 256 + tid];
            s3 += red[(k + 3) * 256 + tid];
        }
        float s = (s0 + s1) + (s2 + s3);

        // ---- tanh, publish h, release flag ------------------------------
        float hnew = tanhf(xp_cur + s);
        g_h[nxt][hw_idx] = hnew;
        __threadfence();
        __syncthreads();                 // all h-writes of this CTA done
        if (tid == 0) st_rel(my_flag, (unsigned)(t + 1));

        // off the critical path:
        out[oi_base + t * HH] = hnew;
        if (t + 1 < TT) xp_cur = __ldg(&out[oi_base + (t + 1) * HH]);

        int tmp = cur; cur = nxt; nxt = nnx; nnx = tmp;
    }
}

// ---------------------------------------------------------------------------
// Launch: init (zero h0 + flags) -> input-projection GEMM -> recurrence
// ---------------------------------------------------------------------------
extern "C" void kernel_launch(void* const* d_in, const int* in_sizes, int n_in,
                              void* d_out, int out_size)
{
    const float* x   = (const float*)d_in[0];
    const float* Wih = (const float*)d_in[1];
    const float* Whh = (const float*)d_in[2];
    const float* bih = (const float*)d_in[3];
    const float* bhh = (const float*)d_in[4];
    float* out = (float*)d_out;
    (void)in_sizes; (void)n_in; (void)out_size;

    cudaFuncSetAttribute(rnn_rec_kernel,
                         cudaFuncAttributeMaxDynamicSharedMemorySize,
                         RSM_BYTES);

    init_kernel<<<128, 256>>>();

    dim3 g1(HH / BN, (BB * TT) / BM);   // (16, 128)
    gemm_xp_kernel<<<g1, 256>>>(x, Wih, bih, bhh, out);

    rnn_rec_kernel<<<RGRID, 256, RSM_BYTES>>>(Whh, out);
}

// round 6
// speedup vs baseline: 1.9022x; 1.0456x over previous
#include <cuda_runtime.h>
#include <cstdio>

// Problem sizes (fixed by the reference)
#define BB 32
#define TT 512
#define EE 1024
#define HH 1024

// ---------------------------------------------------------------------------
// f32x2 packed-FMA helpers (sm_103a FFMA2 path; ptxas only emits via PTX)
// ---------------------------------------------------------------------------
static __device__ __forceinline__ void fma2(unsigned long long &acc,
                                            unsigned long long a,
                                            unsigned long long b) {
    asm("fma.rn.f32x2 %0, %1, %2, %0;" : "+l"(acc) : "l"(a), "l"(b));
}
static __device__ __forceinline__ float2 unpk(unsigned long long v) {
    float2 r;
    asm("mov.b64 {%0, %1}, %2;" : "=f"(r.x), "=f"(r.y) : "l"(v));
    return r;
}
static __device__ __forceinline__ unsigned ld_acq(const unsigned* p) {
    unsigned v;
    asm volatile("ld.acquire.gpu.u32 %0, [%1];" : "=r"(v) : "l"(p));
    return v;
}
static __device__ __forceinline__ void st_rel(unsigned* p, unsigned v) {
    asm volatile("st.release.gpu.u32 [%0], %1;" :: "l"(p), "r"(v) : "memory");
}
static __device__ __forceinline__ unsigned long long gtimer() {
    unsigned long long t;
    asm volatile("mov.u64 %0, %%globaltimer;" : "=l"(t));
    return t;
}

// ---------------------------------------------------------------------------
// Global scratch: 3-deep hidden-state ring + per-CTA monotonic step flags
// ---------------------------------------------------------------------------
__device__ float    g_h[3][BB * HH];
__device__ unsigned g_flag[128 * 32];       // one flag per CTA, 128B stride
__device__ unsigned long long g_t0;         // timing stamp (diagnostics only)

__global__ void init_kernel() {
    int i = blockIdx.x * blockDim.x + threadIdx.x;
    if (i == 0) g_t0 = gtimer();
    if (i < 128 * 32) g_flag[i] = 0u;
    if (i < BB * HH)  g_h[0][i] = 0.0f;   // h_0 = 0
}

// ---------------------------------------------------------------------------
// Phase 1: out[m][n] = sum_k X[m][k] * W[n][k] + (bih[n] + bhh[n])
// M=16384, N=1024, K=1024, NT GEMM, FFMA2, 128x64 tile, double-buffered smem.
// ---------------------------------------------------------------------------
#define BM  128
#define BN  64
#define BK  32
#define LDA 36

__global__ __launch_bounds__(256) void gemm_xp_kernel(
    const float* __restrict__ X, const float* __restrict__ W,
    const float* __restrict__ bih, const float* __restrict__ bhh,
    float* __restrict__ out)
{
    __shared__ __align__(16) float As[2][BM * LDA];
    __shared__ __align__(16) float Bs[2][BN * LDA];

    const int tid = threadIdx.x;
    const int m0  = blockIdx.y * BM;
    const int n0  = blockIdx.x * BN;
    const int r   = tid & 15;
    const int c   = tid >> 4;

    // staging coordinates (same for every tile)
    const int srow = tid >> 3;
    const int skk  = (tid & 7) << 2;

    unsigned long long acc[8][4];
#pragma unroll
    for (int i = 0; i < 8; i++)
#pragma unroll
        for (int j = 0; j < 4; j++) acc[i][j] = 0ull;

    // Preload tile 0
#pragma unroll
    for (int u = 0; u < 4; u++)
        *(float4*)&As[0][(srow + u * 32) * LDA + skk] =
            *(const float4*)&X[(m0 + srow + u * 32) * EE + skk];
#pragma unroll
    for (int u = 0; u < 2; u++)
        *(float4*)&Bs[0][(srow + u * 32) * LDA + skk] =
            *(const float4*)&W[(n0 + srow + u * 32) * EE + skk];
    __syncthreads();

    int cur = 0;
    for (int kt = 0; kt < EE; kt += BK) {
        // Prefetch next tile into registers (latency hidden under compute)
        float4 pa[4], pb[2];
        if (kt + BK < EE) {
#pragma unroll
            for (int u = 0; u < 4; u++)
                pa[u] = *(const float4*)&X[(m0 + srow + u * 32) * EE + kt + BK + skk];
#pragma unroll
            for (int u = 0; u < 2; u++)
                pb[u] = *(const float4*)&W[(n0 + srow + u * 32) * EE + kt + BK + skk];
        }

#pragma unroll
        for (int kk = 0; kk < BK; kk += 4) {
            ulonglong2 av[8];
            ulonglong2 bv[4];
#pragma unroll
            for (int i = 0; i < 8; i++)
                av[i] = *(const ulonglong2*)&As[cur][(r + 16 * i) * LDA + kk];
#pragma unroll
            for (int j = 0; j < 4; j++)
                bv[j] = *(const ulonglong2*)&Bs[cur][(c + 16 * j) * LDA + kk];
#pragma unroll
            for (int i = 0; i < 8; i++) {
#pragma unroll
                for (int j = 0; j < 4; j++) {
                    fma2(acc[i][j], av[i].x, bv[j].x);
                    fma2(acc[i][j], av[i].y, bv[j].y);
                }
            }
        }

        if (kt + BK < EE) {
#pragma unroll
            for (int u = 0; u < 4; u++)
                *(float4*)&As[1 - cur][(srow + u * 32) * LDA + skk] = pa[u];
#pragma unroll
            for (int u = 0; u < 2; u++)
                *(float4*)&Bs[1 - cur][(srow + u * 32) * LDA + skk] = pb[u];
        }
        __syncthreads();
        cur ^= 1;
    }

#pragma unroll
    for (int j = 0; j < 4; j++) {
        int n = n0 + c + 16 * j;
        float bias = bih[n] + bhh[n];
#pragma unroll
        for (int i = 0; i < 8; i++) {
            float2 v = unpk(acc[i][j]);
            out[(m0 + r + 16 * i) * HH + n] = v.x + v.y + bias;
        }
    }
}

// ---------------------------------------------------------------------------
// Phase 2: persistent recurrence. 128 CTAs (co-resident), 256 threads.
//   CTA = batch group gb (8 batches) x col block cb (32 cols), full K = 1024.
//   Thread (c2 = tid&7, ks = tid>>3) computes an 8x4xKt=32 FFMA2 partial.
//
//   Fine-grained pipelined staging: the 8 threads {8*ks + c2} stage chunk ks
//   AND are its only consumers, and all spin on one producer CTA's flag.
//   So there is NO global barrier between stage and compute — just
//   __syncwarp on the 8-lane group. Fast chunks start computing while slow
//   producers finish. Global syncthreads only before the partial-reduce and
//   before publishing the flag.
// ---------------------------------------------------------------------------
#define RGRID   128
#define RW_FLT  (32 * 1024)   // W slice, swizzled     (128 KB)
#define RH_FLT  (8 * 1024)    // h slice, swizzled     ( 32 KB)
#define RR_FLT  (32 * 256)    // reduction partials    ( 32 KB)
#define RSM_BYTES ((RW_FLT + RH_FLT + RR_FLT) * 4)

__global__ __launch_bounds__(256, 1) void rnn_rec_kernel(
    const float* __restrict__ Whh, float* __restrict__ out)
{
    extern __shared__ __align__(16) float sm[];
    float* Ws  = sm;                     // [32 cols][1024] swizzled
    float* hs  = sm + RW_FLT;            // [8 batches][1024] swizzled
    float* red = sm + RW_FLT + RH_FLT;   // [32 ks][256 outputs]

    const int tid = threadIdx.x;
    const int gb  = blockIdx.x >> 5;          // batch group 0..3
    const int c0  = (blockIdx.x & 31) * 32;   // global col base
    const int c2  = tid & 7;                  // col quad 0..7
    const int ks  = tid >> 3;                 // k chunk 0..31

    unsigned long long tstart = 0;
    if (blockIdx.x == 0 && tid == 0) tstart = gtimer();

    // ---- Stage W slice (once), applying the W swizzle -------------------
#pragma unroll 4
    for (int u = 0; u < 32; u++) {
        int f   = tid + u * 256;          // float4 index 0..8191
        int col = f >> 8;                 // local col 0..31
        int g   = f & 255;                // granule
        int gp  = (g & ~7) | ((g ^ (g >> 3) ^ col) & 7);
        float4 v = *(const float4*)&Whh[(c0 + col) * HH + g * 4];
        *(float4*)&Ws[col * 1024 + gp * 4] = v;
    }

    // Per-thread invariant offsets
    const int kbase = ks * 32;            // float offset of this k chunk
    const int sxh   = ks & 7;             // h swizzle term
    int sxj[4];
    const float* wb[4];
#pragma unroll
    for (int j = 0; j < 4; j++) {
        int col = c2 * 4 + j;
        sxj[j] = (ks ^ col) & 7;
        wb[j]  = &Ws[col * 1024 + kbase];
    }
    const float* hb = &hs[kbase];

    // Staging: thread tid copies granule tid (chunk ks = tid>>3), whose sole
    // producer is CTA (gb, ks). 8-lane consumer group = threads 8ks..8ks+7.
    const unsigned* my_src_flag = &g_flag[(gb * 32 + ks) * 32];
    unsigned*       my_flag     = &g_flag[blockIdx.x * 32];
    const int g_st  = tid;
    const int gp_st = (g_st & ~7) | ((g_st ^ (g_st >> 3)) & 7);
    const unsigned grp_mask = 0xFFu << (((tid >> 3) & 3) * 8);

    // Epilogue output mapping: o = tid = b*32 + colL (coalesced)
    const int b_out   = tid >> 5;
    const int colL    = tid & 31;
    const int oi_base = (gb * 8 + b_out) * TT * HH + (c0 + colL);
    const int hw_idx  = (gb * 8 + b_out) * HH + (c0 + colL);

    int cur = 0, nxt = 1, nnx = 2;        // rotating ring indices
    float xp_cur = __ldg(&out[oi_base]);  // prefetch xp for t = 0

    __syncthreads();   // Ws fully staged before first microloop

    for (int t = 0; t < TT; t++) {
        // ---- Wait for this chunk's producer, stage 8 granules, group sync
        if (t) {
            while (ld_acq(my_src_flag) < (unsigned)t) { }
        }
        {
            const float4* hsrc =
                (const float4*)(g_h[cur] + gb * 8 * HH) + g_st;
            float4* hdst = (float4*)&hs[gp_st * 4];
#pragma unroll
            for (int u = 0; u < 8; u++) {
                float4 v = __ldcg(hsrc + u * 256);
                *(float4*)((char*)hdst + u * 4096) = v;
            }
        }
        __syncwarp(grp_mask);

        // ---- 8x4 x Kt=32 FFMA2 microtile --------------------------------
        unsigned long long acc[8][4];
#pragma unroll
        for (int i = 0; i < 8; i++)
#pragma unroll
            for (int j = 0; j < 4; j++) acc[i][j] = 0ull;

#pragma unroll
        for (int kq = 0; kq < 8; kq++) {
            ulonglong2 hv[8];
            ulonglong2 wv[4];
            int ho = ((kq ^ sxh) & 7) * 4;
#pragma unroll
            for (int i = 0; i < 8; i++)
                hv[i] = *(const ulonglong2*)(hb + i * 1024 + ho);
#pragma unroll
            for (int j = 0; j < 4; j++)
                wv[j] = *(const ulonglong2*)(wb[j] + ((kq ^ sxj[j]) & 7) * 4);
#pragma unroll
            for (int i = 0; i < 8; i++) {
#pragma unroll
                for (int j = 0; j < 4; j++) {
                    fma2(acc[i][j], hv[i].x, wv[j].x);
                    fma2(acc[i][j], hv[i].y, wv[j].y);
                }
            }
        }

        // ---- Reduce KS=32 partials through smem -------------------------
#pragma unroll
        for (int i = 0; i < 8; i++) {
            float2 a0 = unpk(acc[i][0]), a1 = unpk(acc[i][1]);
            float2 a2 = unpk(acc[i][2]), a3 = unpk(acc[i][3]);
            float4 v;
            v.x = a0.x + a0.y; v.y = a1.x + a1.y;
            v.z = a2.x + a2.y; v.w = a3.x + a3.y;
            *(float4*)&red[ks * 256 + i * 32 + c2 * 4] = v;
        }
        __syncthreads();

        float s0 = 0.f, s1 = 0.f, s2 = 0.f, s3 = 0.f;
#pragma unroll
        for (int k = 0; k < 32; k += 4) {
            s0 += red[(k + 0) * 256 + tid];
            s1 += red[(k + 1) * 256 + tid];
            s2 += red[(k + 2) * 256 + tid];
            s3 += red[(k + 3) * 256 + tid];
        }
        float s = (s0 + s1) + (s2 + s3);

        // ---- tanh, publish h, release flag ------------------------------
        float hnew = tanhf(xp_cur + s);
        g_h[nxt][hw_idx] = hnew;
        __syncthreads();                 // all h-writes of this CTA done
        if (tid == 0) st_rel(my_flag, (unsigned)(t + 1));

        // off the critical path:
        out[oi_base + t * HH] = hnew;
        if (t + 1 < TT) xp_cur = __ldg(&out[oi_base + (t + 1) * HH]);

        int tmp = cur; cur = nxt; nxt = nnx; nnx = tmp;
    }

    if (blockIdx.x == 0 && tid == 0) {
        unsigned long long tend = gtimer();
        printf("[prof] pre_rec=%lluns rec=%lluns\n",
               (unsigned long long)(tstart - g_t0),
               (unsigned long long)(tend - tstart));
    }
}

// ---------------------------------------------------------------------------
// Launch: init (zero h0 + flags) -> input-projection GEMM -> recurrence
// ---------------------------------------------------------------------------
extern "C" void kernel_launch(void* const* d_in, const int* in_sizes, int n_in,
                              void* d_out, int out_size)
{
    const float* x   = (const float*)d_in[0];
    const float* Wih = (const float*)d_in[1];
    const float* Whh = (const float*)d_in[2];
    const float* bih = (const float*)d_in[3];
    const float* bhh = (const float*)d_in[4];
    float* out = (float*)d_out;
    (void)in_sizes; (void)n_in; (void)out_size;

    cudaFuncSetAttribute(rnn_rec_kernel,
                         cudaFuncAttributeMaxDynamicSharedMemorySize,
                         RSM_BYTES);

    init_kernel<<<128, 256>>>();

    dim3 g1(HH / BN, (BB * TT) / BM);   // (16, 128)
    gemm_xp_kernel<<<g1, 256>>>(x, Wih, bih, bhh, out);

    rnn_rec_kernel<<<RGRID, 256, RSM_BYTES>>>(Whh, out);
}